// round 1
// baseline (speedup 1.0000x reference)
#include <cuda_runtime.h>

#define NO   20000
#define KC   11
#define DIM  256
#define OUTF 128
#define KSEL 10

// ---- scratch (no allocations allowed) ----
__device__ float  g_wa2[2 * DIM];   // W @ A[OUTF:, 0], length 512
__device__ double g_sumA;           // sum over selected dmc rows
__device__ double g_sumB;           // sum over dropped dmc rows

// Kernel 1: wa2[d] = sum_f W[d,f] * A[OUTF+f]; zero accumulators (graph-replay safe)
__global__ void prep_kernel(const float* __restrict__ W, const float* __restrict__ A) {
    int d = threadIdx.x;                  // 0..511
    const float* wrow = W + (size_t)d * OUTF;
    const float* a2   = A + OUTF;
    float acc = 0.f;
#pragma unroll 8
    for (int f = 0; f < OUTF; ++f) acc += wrow[f] * a2[f];
    g_wa2[d] = acc;
    if (d == 0) { g_sumA = 0.0; g_sumB = 0.0; }
}

// Kernel 2: one CTA per row n, 11 warps (one per candidate k)
__global__ void __launch_bounds__(352) main_kernel(
    const float* __restrict__ Cand,     // [NO, KC, DIM]
    const float* __restrict__ ndist,    // [NO, KC]
    const int*   __restrict__ nind,     // [NO, KC]
    const float* __restrict__ dtrain,   // [NT, DIM]
    float*       __restrict__ out)
{
    __shared__ __align__(16) float sC[KC][DIM];  // candidate tile (11.25 KB)
    __shared__ __align__(16) float s_wa[2 * DIM];
    __shared__ float sScore[KC];
    __shared__ float sRow[KC];

    const int n    = blockIdx.x;
    const int tid  = threadIdx.x;
    const int w    = tid >> 5;    // 0..10 candidate index
    const int lane = tid & 31;

    // stage wa2 into smem
    for (int i = tid; i < 2 * DIM; i += 352) s_wa[i] = g_wa2[i];

    // early global loads (MLP): lane covers dims [lane*4, lane*4+4) and [128+lane*4, ...)
    const float4* cp = (const float4*)(Cand + ((size_t)n * KC + w) * DIM);
    float4 c0 = cp[lane];
    float4 c1 = cp[lane + 32];
    const int ind = nind[n * KC + w];
    const float4* dp = (const float4*)(dtrain + (size_t)ind * DIM);
    float4 d0 = dp[lane];
    float4 d1 = dp[lane + 32];

    __syncthreads();

    const float4* w4 = (const float4*)s_wa;
    float4 wl0 = w4[lane],      wl1 = w4[lane + 32];   // wa2[0:256]
    float4 wh0 = w4[lane + 64], wh1 = w4[lane + 96];   // wa2[256:512]

    float sc = c0.x*wl0.x + c0.y*wl0.y + c0.z*wl0.z + c0.w*wl0.w
             + c1.x*wl1.x + c1.y*wl1.y + c1.z*wl1.z + c1.w*wl1.w
             + d0.x*wh0.x + d0.y*wh0.y + d0.z*wh0.z + d0.w*wh0.w
             + d1.x*wh1.x + d1.y*wh1.y + d1.z*wh1.z + d1.w*wh1.w;
    float rs = d0.x + d0.y + d0.z + d0.w + d1.x + d1.y + d1.z + d1.w;

#pragma unroll
    for (int off = 16; off; off >>= 1) {
        sc += __shfl_down_sync(0xffffffffu, sc, off);
        rs += __shfl_down_sync(0xffffffffu, rs, off);
    }

    // stage candidate row in smem for the output copy
    ((float4*)sC[w])[lane]      = c0;
    ((float4*)sC[w])[lane + 32] = c1;
    if (lane == 0) { sScore[w] = sc; sRow[w] = rs; }
    __syncthreads();

    // dropped index = argmin of score; tie -> larger index (top_k keeps lower indices)
    float minv = sScore[0];
    int   drop = 0;
#pragma unroll
    for (int kk = 1; kk < KC; ++kk) {
        float v = sScore[kk];
        if (v <= minv) { minv = v; drop = kk; }
    }

    if (w < KSEL) {
        // Cand_sel[n, w, :] = Candidate[n, src, :]
        const int src = w + (w >= drop ? 1 : 0);
        float4* op = (float4*)(out + ((size_t)n * KSEL + w) * DIM);
        op[lane]      = ((const float4*)sC[src])[lane];
        op[lane + 32] = ((const float4*)sC[src])[lane + 32];
    } else {
        if (lane < KSEL) {
            const int src = lane + (lane >= drop ? 1 : 0);
            const size_t ND_OFF = (size_t)NO * KSEL * DIM;
            const size_t NI_OFF = ND_OFF + (size_t)NO * KSEL;
            out[ND_OFF + (size_t)n * KSEL + lane] = ndist[n * KC + src];
            out[NI_OFF + (size_t)n * KSEL + lane] = (float)nind[n * KC + src];
        } else if (lane == KSEL) {
            float sa = 0.f;
#pragma unroll
            for (int kk = 0; kk < KC; ++kk) if (kk != drop) sa += sRow[kk];
            atomicAdd(&g_sumA, (double)sa);
            atomicAdd(&g_sumB, (double)sRow[drop]);
        }
    }
}

// Kernel 3: write the two scalars
__global__ void finish_kernel(float* __restrict__ out) {
    const size_t A_OFF = (size_t)NO * KSEL * DIM + 2ull * NO * KSEL;
    out[A_OFF]     = (float)(g_sumA / ((double)NO * KSEL));
    out[A_OFF + 1] = (float)(g_sumB / (double)NO);
}

extern "C" void kernel_launch(void* const* d_in, const int* in_sizes, int n_in,
                              void* d_out, int out_size) {
    (void)out_size;
    // Identify inputs by element count (robust to presence/absence of the scalar `test`):
    //   Candidate    = 20000*11*256 = 56,320,000
    //   data_m_train = 100000*256   = 25,600,000
    //   neigh_dist / neigh_ind      =    220,000 (dist first in metadata order)
    //   W            = 512*128      =     65,536
    //   A            = 256
    const float* Cand   = nullptr;
    const float* ndist  = nullptr;
    const int*   nind   = nullptr;
    const float* dtrain = nullptr;
    const float* W      = nullptr;
    const float* A      = nullptr;
    for (int i = 0; i < n_in; ++i) {
        const int s = in_sizes[i];
        if      (s == 56320000) Cand   = (const float*)d_in[i];
        else if (s == 25600000) dtrain = (const float*)d_in[i];
        else if (s == 220000) {
            if (!ndist) ndist = (const float*)d_in[i];
            else        nind  = (const int*)d_in[i];
        }
        else if (s == 65536)    W      = (const float*)d_in[i];
        else if (s == 256)      A      = (const float*)d_in[i];
    }

    float* out = (float*)d_out;
    prep_kernel<<<1, 2 * DIM>>>(W, A);
    main_kernel<<<NO, 352>>>(Cand, ndist, nind, dtrain, out);
    finish_kernel<<<1, 1>>>(out);
}

// round 2
// speedup vs baseline: 1.1200x; 1.1200x over previous
#include <cuda_runtime.h>

#define NO   20000
#define KC   11
#define DIM  256
#define OUTF 128
#define KSEL 10

// ---- scratch (no allocations allowed) ----
__device__ float        g_wa2[2 * DIM];   // W @ A[OUTF:, 0], length 512
__device__ double       g_sumA;           // sum over selected dmc rows
__device__ double       g_sumB;           // sum over dropped dmc rows
__device__ unsigned int g_done;           // completed-CTA counter

// Kernel 1: wa2[d] = sum_f W[d,f] * A[OUTF+f]; one warp per d (512 warps).
// Also zeroes the accumulators + counter (graph-replay safe).
__global__ void __launch_bounds__(256) prep_kernel(const float* __restrict__ W,
                                                   const float* __restrict__ A) {
    const int warp = (blockIdx.x * blockDim.x + threadIdx.x) >> 5;  // 0..511 = d
    const int lane = threadIdx.x & 31;

    const float* wrow = W + (size_t)warp * OUTF;
    const float* a2   = A + OUTF;
    float acc = wrow[lane]      * a2[lane]
              + wrow[lane + 32] * a2[lane + 32]
              + wrow[lane + 64] * a2[lane + 64]
              + wrow[lane + 96] * a2[lane + 96];
#pragma unroll
    for (int off = 16; off; off >>= 1)
        acc += __shfl_down_sync(0xffffffffu, acc, off);
    if (lane == 0) g_wa2[warp] = acc;

    if (blockIdx.x == 0 && threadIdx.x == 0) {
        g_sumA = 0.0; g_sumB = 0.0; g_done = 0u;
    }
}

// Kernel 2: one CTA per row n, 11 warps (one per candidate k)
__global__ void __launch_bounds__(352) main_kernel(
    const float* __restrict__ Cand,     // [NO, KC, DIM]
    const float* __restrict__ ndist,    // [NO, KC]
    const int*   __restrict__ nind,     // [NO, KC]
    const float* __restrict__ dtrain,   // [NT, DIM]
    float*       __restrict__ out)
{
    __shared__ __align__(16) float sC[KC][DIM];  // candidate tile (11.25 KB)
    __shared__ __align__(16) float s_wa[2 * DIM];
    __shared__ float sScore[KC];
    __shared__ float sRow[KC];

    const int n    = blockIdx.x;
    const int tid  = threadIdx.x;
    const int w    = tid >> 5;    // 0..10 candidate index
    const int lane = tid & 31;

    // stage wa2 into smem
    for (int i = tid; i < 2 * DIM; i += 352) s_wa[i] = g_wa2[i];

    // early global loads (MLP): lane covers dims [lane*4, lane*4+4) and [128+lane*4, ...)
    const float4* cp = (const float4*)(Cand + ((size_t)n * KC + w) * DIM);
    float4 c0 = cp[lane];
    float4 c1 = cp[lane + 32];
    const int ind = nind[n * KC + w];
    const float4* dp = (const float4*)(dtrain + (size_t)ind * DIM);
    float4 d0 = dp[lane];
    float4 d1 = dp[lane + 32];

    __syncthreads();

    const float4* w4 = (const float4*)s_wa;
    float4 wl0 = w4[lane],      wl1 = w4[lane + 32];   // wa2[0:256]
    float4 wh0 = w4[lane + 64], wh1 = w4[lane + 96];   // wa2[256:512]

    float sc = c0.x*wl0.x + c0.y*wl0.y + c0.z*wl0.z + c0.w*wl0.w
             + c1.x*wl1.x + c1.y*wl1.y + c1.z*wl1.z + c1.w*wl1.w
             + d0.x*wh0.x + d0.y*wh0.y + d0.z*wh0.z + d0.w*wh0.w
             + d1.x*wh1.x + d1.y*wh1.y + d1.z*wh1.z + d1.w*wh1.w;
    float rs = d0.x + d0.y + d0.z + d0.w + d1.x + d1.y + d1.z + d1.w;

#pragma unroll
    for (int off = 16; off; off >>= 1) {
        sc += __shfl_down_sync(0xffffffffu, sc, off);
        rs += __shfl_down_sync(0xffffffffu, rs, off);
    }

    // stage candidate row in smem for the output copy
    ((float4*)sC[w])[lane]      = c0;
    ((float4*)sC[w])[lane + 32] = c1;
    if (lane == 0) { sScore[w] = sc; sRow[w] = rs; }
    __syncthreads();

    // dropped index = argmin of score; tie -> larger index (top_k keeps lower indices)
    float minv = sScore[0];
    int   drop = 0;
#pragma unroll
    for (int kk = 1; kk < KC; ++kk) {
        float v = sScore[kk];
        if (v <= minv) { minv = v; drop = kk; }
    }

    if (w < KSEL) {
        // Cand_sel[n, w, :] = Candidate[n, src, :]
        const int src = w + (w >= drop ? 1 : 0);
        float4* op = (float4*)(out + ((size_t)n * KSEL + w) * DIM);
        op[lane]      = ((const float4*)sC[src])[lane];
        op[lane + 32] = ((const float4*)sC[src])[lane + 32];
    } else {
        if (lane < KSEL) {
            const int src = lane + (lane >= drop ? 1 : 0);
            const size_t ND_OFF = (size_t)NO * KSEL * DIM;
            const size_t NI_OFF = ND_OFF + (size_t)NO * KSEL;
            out[ND_OFF + (size_t)n * KSEL + lane] = ndist[n * KC + src];
            out[NI_OFF + (size_t)n * KSEL + lane] = (float)nind[n * KC + src];
        } else if (lane == KSEL) {
            float sa = 0.f;
#pragma unroll
            for (int kk = 0; kk < KC; ++kk) if (kk != drop) sa += sRow[kk];
            atomicAdd(&g_sumA, (double)sa);
            atomicAdd(&g_sumB, (double)sRow[drop]);
            __threadfence();
            // last CTA to finish writes the two scalar outputs
            unsigned int prev = atomicAdd(&g_done, 1u);
            if (prev == NO - 1) {
                const size_t A_OFF = (size_t)NO * KSEL * DIM + 2ull * NO * KSEL;
                out[A_OFF]     = (float)(g_sumA / ((double)NO * KSEL));
                out[A_OFF + 1] = (float)(g_sumB / (double)NO);
            }
        }
    }
}

extern "C" void kernel_launch(void* const* d_in, const int* in_sizes, int n_in,
                              void* d_out, int out_size) {
    (void)out_size;
    // Identify inputs by element count (robust to presence/absence of the scalar `test`):
    //   Candidate    = 20000*11*256 = 56,320,000
    //   data_m_train = 100000*256   = 25,600,000
    //   neigh_dist / neigh_ind      =    220,000 (dist first in metadata order)
    //   W            = 512*128      =     65,536
    //   A            = 256
    const float* Cand   = nullptr;
    const float* ndist  = nullptr;
    const int*   nind   = nullptr;
    const float* dtrain = nullptr;
    const float* W      = nullptr;
    const float* A      = nullptr;
    for (int i = 0; i < n_in; ++i) {
        const int s = in_sizes[i];
        if      (s == 56320000) Cand   = (const float*)d_in[i];
        else if (s == 25600000) dtrain = (const float*)d_in[i];
        else if (s == 220000) {
            if (!ndist) ndist = (const float*)d_in[i];
            else        nind  = (const int*)d_in[i];
        }
        else if (s == 65536)    W      = (const float*)d_in[i];
        else if (s == 256)      A      = (const float*)d_in[i];
    }

    float* out = (float*)d_out;
    prep_kernel<<<64, 256>>>(W, A);        // 512 warps: one per wa2 element
    main_kernel<<<NO, 352>>>(Cand, ndist, nind, dtrain, out);
}